// round 6
// baseline (speedup 1.0000x reference)
#include <cuda_runtime.h>
#include <math.h>
#include <cstdint>

#define BB 8
#define TT 2048
#define CC 512
#define HH 64
#define MTOT (BB*TT)
#define SCALE 0.044194173824159216f   // 512^-0.5 (folded into Wq)

// tf32-rounded intermediates (Q pre-scaled by SCALE)
__device__ float g_Q[MTOT*HH];
__device__ float g_K[MTOT*HH];
__device__ float g_V[MTOT*HH];

__device__ __forceinline__ float rna(float x){
    uint32_t u = __float_as_uint(x), o;
    asm("cvt.rna.tf32.f32 %0, %1;" : "=r"(o) : "r"(u));
    return __uint_as_float(o);
}
__device__ __forceinline__ void mma8(float* d, const uint32_t* a, uint32_t b0, uint32_t b1){
    asm volatile(
        "mma.sync.aligned.m16n8k8.row.col.f32.tf32.tf32.f32 "
        "{%0,%1,%2,%3}, {%4,%5,%6,%7}, {%8,%9}, {%0,%1,%2,%3};"
        : "+f"(d[0]), "+f"(d[1]), "+f"(d[2]), "+f"(d[3])
        : "r"(a[0]), "r"(a[1]), "r"(a[2]), "r"(a[3]), "r"(b0), "r"(b1));
}
__device__ __forceinline__ uint32_t f2u(float x){ return __float_as_uint(x); }
__device__ __forceinline__ uint32_t smem_u32(const void* p){
    uint32_t a;
    asm("{ .reg .u64 t; cvta.to.shared.u64 t, %1; cvt.u32.u64 %0, t; }" : "=r"(a) : "l"(p));
    return a;
}
#define CPA16(dst, src) asm volatile("cp.async.cg.shared.global [%0], [%1], 16;" :: "r"(dst), "l"(src))
#define CPA_COMMIT()    asm volatile("cp.async.commit_group;" ::: "memory")
#define CPA_WAIT(n)     asm volatile("cp.async.wait_group %0;" :: "n"(n) : "memory")

// ---------------------------------------------------------------------------
// Projection: [Q|K|V](16384,192) = x(16384,512) @ [Wq*s|Wk|Wv](512,192)
// 256 blocks x 512 threads, 64 rows/block, 2 blocks/SM.
// Warp grid: 2 row-groups (32 rows) x 8 col-groups (24 cols = 3 j-tiles).
// ---------------------------------------------------------------------------
#define XST 68
#define WST 200
#define PJ_SMEM ((64*XST + 64*WST)*4)   // 68,608 B

__global__ __launch_bounds__(512, 2) void proj_mma(
    const float* __restrict__ x,  const float* __restrict__ Wq,
    const float* __restrict__ Wk, const float* __restrict__ Wv)
{
    extern __shared__ float sm[];
    float* xs = sm;              // 64 x 68
    float* ws = sm + 64*XST;     // 64 x 200 (cols 0-63 Wq*s, 64-127 Wk, 128-191 Wv)

    const int tid  = threadIdx.x;
    const int w    = tid >> 5;
    const int lane = tid & 31;
    const int lq   = lane >> 2;
    const int lr   = lane & 3;
    const int rw   = w & 1;          // row group (32 rows)
    const int cw   = w >> 1;         // col group (24 cols = 3 j-tiles)
    const int g0   = blockIdx.x * 64;

    float acc[2][3][4];
    #pragma unroll
    for (int m = 0; m < 2; m++)
        #pragma unroll
        for (int j = 0; j < 3; j++)
            #pragma unroll
            for (int t = 0; t < 4; t++) acc[m][j][t] = 0.f;

    for (int kc = 0; kc < 8; kc++){
        __syncthreads();
        {   // stage x chunk [64 x 64], rounded
            const float* xg = x + (size_t)g0 * CC + kc*64;
            #pragma unroll
            for (int it = 0; it < 2; it++){
                int r = (tid >> 4) + it*32, c4 = (tid & 15) * 4;
                float4 v = *(const float4*)(xg + (size_t)r*CC + c4);
                v.x = rna(v.x); v.y = rna(v.y); v.z = rna(v.z); v.w = rna(v.w);
                *(float4*)(xs + r*XST + c4) = v;
            }
        }
        // stage W chunk [64 x 192], rounded (+SCALE on Wq)
        #pragma unroll
        for (int it = 0; it < 6; it++){
            int i = tid + it*512;
            int k = i / 48, c4 = (i % 48) * 4;
            int g = c4 >> 6, cc = c4 & 63;
            const float* Wg = (g == 0) ? Wq : (g == 1) ? Wk : Wv;
            float s = (g == 0) ? SCALE : 1.f;
            float4 v = *(const float4*)(Wg + (size_t)(kc*64 + k)*HH + cc);
            v.x = rna(v.x*s); v.y = rna(v.y*s); v.z = rna(v.z*s); v.w = rna(v.w*s);
            *(float4*)(ws + k*WST + c4) = v;
        }
        __syncthreads();

        #pragma unroll
        for (int ks = 0; ks < 8; ks++){
            uint32_t a[2][4];
            #pragma unroll
            for (int m = 0; m < 2; m++){
                const float* ab = xs + (32*rw + 16*m + lq)*XST + ks*8 + lr;
                a[m][0] = f2u(ab[0]);   a[m][1] = f2u(ab[8*XST]);
                a[m][2] = f2u(ab[4]);   a[m][3] = f2u(ab[8*XST + 4]);
            }
            #pragma unroll
            for (int j = 0; j < 3; j++){
                const float* bb = ws + (ks*8 + lr)*WST + 24*cw + j*8 + lq;
                uint32_t b0 = f2u(bb[0]), b1 = f2u(bb[4*WST]);
                mma8(acc[0][j], a[0], b0, b1);
                mma8(acc[1][j], a[1], b0, b1);
            }
        }
    }

    // epilogue: round + store
    #pragma unroll
    for (int m = 0; m < 2; m++){
        const int row = g0 + 32*rw + 16*m + lq;
        #pragma unroll
        for (int j = 0; j < 3; j++){
            int c = 24*cw + j*8 + 2*lr;
            int g = c >> 6, cc = c & 63;
            float* dst = (g == 0) ? g_Q : (g == 1) ? g_K : g_V;
            float2 v0 = { rna(acc[m][j][0]), rna(acc[m][j][1]) };
            float2 v1 = { rna(acc[m][j][2]), rna(acc[m][j][3]) };
            *(float2*)(dst + (size_t)row*HH + cc)       = v0;
            *(float2*)(dst + (size_t)(row + 8)*HH + cc) = v1;
        }
    }
}

// ---------------------------------------------------------------------------
// Attention: 128 blocks x 512 threads; 128 q rows/block, 16 tiles of 128 keys.
// Warp grid: S 4 (rows of 32) x 4 (keys of 32); PV 4 (rows of 32) x 4 (hcols of 16).
// K double-buffered, V single-buffered (separate cp.async groups).
// smem floats: lbuf[4][128] @0, Qs@512, Ks0, Ks1, Vs, Ps.
// ---------------------------------------------------------------------------
#define KST 68
#define VST 72
#define PST 132
#define QST 68
#define OF_LB 0
#define OF_Q  512
#define OF_K0 (OF_Q  + 128*QST)   //  9216
#define OF_K1 (OF_K0 + 128*KST)   // 17920
#define OF_V  (OF_K1 + 128*KST)   // 26624
#define OF_P  (OF_V  + 128*VST)   // 35840
#define AT_SMEM ((OF_P + 128*PST)*4)   // 210,944 B

__global__ __launch_bounds__(512, 1) void attn_mma(float* __restrict__ out)
{
    extern __shared__ float sm[];
    const uint32_t sb = smem_u32(sm);
    float* Qs = sm + OF_Q;
    float* Ps = sm + OF_P;
    float* Vs = sm + OF_V;

    const int tid  = threadIdx.x;
    const int w    = tid >> 5;
    const int lane = tid & 31;
    const int lq   = lane >> 2;
    const int lr   = lane & 3;
    const int rw   = w & 3;          // row group (32 rows), both GEMMs
    const int cw   = w >> 2;         // col group: 32 keys (S) / 16 hcols (PV)
    const int g0   = blockIdx.x * 128;
    const int b    = g0 >> 11;

    const int stg_r  = tid >> 4;            // 0..31
    const int stg_c4 = (tid & 15) * 4;

    // prefetch K tile 0 (group 0)
    {
        const float* Kg = g_K + (size_t)(b*TT) * HH;
        #pragma unroll
        for (int it = 0; it < 4; it++){
            int r = stg_r + it*32;
            CPA16(sb + (OF_K0 + r*KST + stg_c4)*4, Kg + (size_t)r*HH + stg_c4);
        }
        CPA_COMMIT();
    }
    // stage Q (already tf32 + pre-scaled)
    {
        const float* Qg = g_Q + (size_t)g0 * HH;
        #pragma unroll
        for (int it = 0; it < 4; it++){
            int r = stg_r + it*32;
            *(float4*)(Qs + r*QST + stg_c4) = *(const float4*)(Qg + (size_t)r*HH + stg_c4);
        }
    }

    float oacc[2][2][4];
    #pragma unroll
    for (int m = 0; m < 2; m++)
        #pragma unroll
        for (int j = 0; j < 2; j++)
            #pragma unroll
            for (int t = 0; t < 4; t++) oacc[m][j][t] = 0.f;
    float ls[2][2] = {{0.f,0.f},{0.f,0.f}};

    for (int kt = 0; kt < 16; kt++){
        if (kt) __syncthreads();   // PV(kt-1) done: V, P, old-K buffers free
        else    __syncthreads();   // Q staging visible

        // issue V(kt) (own group), then K(kt+1) (own group)
        {
            const float* Vg = g_V + (size_t)(b*TT + kt*128) * HH;
            #pragma unroll
            for (int it = 0; it < 4; it++){
                int r = stg_r + it*32;
                CPA16(sb + (OF_V + r*VST + stg_c4)*4, Vg + (size_t)r*HH + stg_c4);
            }
            CPA_COMMIT();
        }
        if (kt + 1 < 16){
            const uint32_t kofs = ((kt+1) & 1) ? OF_K1 : OF_K0;
            const float* Kg = g_K + (size_t)(b*TT + (kt+1)*128) * HH;
            #pragma unroll
            for (int it = 0; it < 4; it++){
                int r = stg_r + it*32;
                CPA16(sb + (kofs + r*KST + stg_c4)*4, Kg + (size_t)r*HH + stg_c4);
            }
        }
        CPA_COMMIT();

        CPA_WAIT(2);               // K(kt) (and everything older) complete
        __syncthreads();

        const float* Ks = sm + ((kt & 1) ? OF_K1 : OF_K0);

        // ---- S = Q @ K^T : rows 32*rw.., keys 32*cw.. (4 n-tiles) ----
        float s[2][4][4];
        #pragma unroll
        for (int m = 0; m < 2; m++)
            #pragma unroll
            for (int j = 0; j < 4; j++)
                #pragma unroll
                for (int t = 0; t < 4; t++) s[m][j][t] = 0.f;

        #pragma unroll
        for (int ks = 0; ks < 8; ks++){
            uint32_t a[2][4];
            #pragma unroll
            for (int m = 0; m < 2; m++){
                const float* ab = Qs + (32*rw + 16*m + lq)*QST + ks*8 + lr;
                a[m][0] = f2u(ab[0]);   a[m][1] = f2u(ab[8*QST]);
                a[m][2] = f2u(ab[4]);   a[m][3] = f2u(ab[8*QST + 4]);
            }
            #pragma unroll
            for (int nt = 0; nt < 4; nt++){
                const float* bb = Ks + (32*cw + nt*8 + lq)*KST + ks*8 + lr;
                uint32_t b0 = f2u(bb[0]), b1 = f2u(bb[4]);
                mma8(s[0][nt], a[0], b0, b1);
                mma8(s[1][nt], a[1], b0, b1);
            }
        }

        // ---- softmax (no max): exp, partial row sums, write P ----
        #pragma unroll
        for (int m = 0; m < 2; m++){
            float* p0 = Ps + (32*rw + 16*m + lq)*PST + 32*cw + 2*lr;
            float* p1 = p0 + 8*PST;
            #pragma unroll
            for (int nt = 0; nt < 4; nt++){
                float e0 = __expf(s[m][nt][0]);
                float e1 = __expf(s[m][nt][1]);
                float e2 = __expf(s[m][nt][2]);
                float e3 = __expf(s[m][nt][3]);
                ls[m][0] += e0 + e1;
                ls[m][1] += e2 + e3;
                float2 w0 = { rna(e0), rna(e1) };
                float2 w1 = { rna(e2), rna(e3) };
                *(float2*)(p0 + nt*8) = w0;
                *(float2*)(p1 + nt*8) = w1;
            }
        }
        CPA_WAIT(1);               // V(kt) complete (K(kt+1) may still fly)
        __syncthreads();           // P + V visible block-wide

        // ---- O += P @ V : rows 32*rw.., hcols 16*cw.. (2 n-tiles), K=128 ----
        #pragma unroll
        for (int ks = 0; ks < 16; ks++){
            uint32_t a[2][4];
            #pragma unroll
            for (int m = 0; m < 2; m++){
                const float* ab = Ps + (32*rw + 16*m + lq)*PST + ks*8 + lr;
                a[m][0] = f2u(ab[0]);   a[m][1] = f2u(ab[8*PST]);
                a[m][2] = f2u(ab[4]);   a[m][3] = f2u(ab[8*PST + 4]);
            }
            #pragma unroll
            for (int nt = 0; nt < 2; nt++){
                const float* bb = Vs + (ks*8 + lr)*VST + 16*cw + nt*8 + lq;
                uint32_t b0 = f2u(bb[0]), b1 = f2u(bb[4*VST]);
                mma8(oacc[0][nt], a[0], b0, b1);
                mma8(oacc[1][nt], a[1], b0, b1);
            }
        }
    }

    // ---- finalize row sums: quad-reduce, combine the 4 col-warps ----
    float* lbuf = sm + OF_LB;   // [4][128]
    #pragma unroll
    for (int m = 0; m < 2; m++)
        #pragma unroll
        for (int h = 0; h < 2; h++){
            float v = ls[m][h];
            v += __shfl_xor_sync(0xffffffffu, v, 1);
            v += __shfl_xor_sync(0xffffffffu, v, 2);
            ls[m][h] = v;
        }
    __syncthreads();
    #pragma unroll
    for (int m = 0; m < 2; m++){
        lbuf[cw*128 + 32*rw + 16*m + lq]     = ls[m][0];
        lbuf[cw*128 + 32*rw + 16*m + lq + 8] = ls[m][1];
    }
    __syncthreads();

    #pragma unroll
    for (int m = 0; m < 2; m++){
        const int row = 32*rw + 16*m + lq;
        const float inv0 = 1.f / (lbuf[row]     + lbuf[128 + row]     + lbuf[256 + row]     + lbuf[384 + row]);
        const float inv1 = 1.f / (lbuf[row + 8] + lbuf[128 + row + 8] + lbuf[256 + row + 8] + lbuf[384 + row + 8]);
        #pragma unroll
        for (int nt = 0; nt < 2; nt++){
            int col = 16*cw + nt*8 + 2*lr;
            float2 v0 = { oacc[m][nt][0]*inv0, oacc[m][nt][1]*inv0 };
            float2 v1 = { oacc[m][nt][2]*inv1, oacc[m][nt][3]*inv1 };
            *(float2*)(out + (size_t)(g0 + row)*HH + col)     = v0;
            *(float2*)(out + (size_t)(g0 + row + 8)*HH + col) = v1;
        }
    }
}

// ---------------------------------------------------------------------------
extern "C" void kernel_launch(void* const* d_in, const int* in_sizes, int n_in,
                              void* d_out, int out_size)
{
    const float* x  = (const float*)d_in[0];
    const float* Wq = (const float*)d_in[1];
    const float* Wk = (const float*)d_in[2];
    const float* Wv = (const float*)d_in[3];
    float* out = (float*)d_out;

    cudaFuncSetAttribute(proj_mma, cudaFuncAttributeMaxDynamicSharedMemorySize, PJ_SMEM);
    proj_mma<<<MTOT/64, 512, PJ_SMEM>>>(x, Wq, Wk, Wv);

    cudaFuncSetAttribute(attn_mma, cudaFuncAttributeMaxDynamicSharedMemorySize, AT_SMEM);
    attn_mma<<<MTOT/128, 512, AT_SMEM>>>(out);
}

// round 7
// speedup vs baseline: 1.0008x; 1.0008x over previous
#include <cuda_runtime.h>
#include <math.h>
#include <cstdint>

#define BB 8
#define TT 2048
#define CC 512
#define HH 64
#define MTOT (BB*TT)
#define SCALE 0.044194173824159216f   // 512^-0.5 (folded into Wq)

// tf32-rounded intermediates (Q pre-scaled by SCALE)
__device__ float g_Q[MTOT*HH];
__device__ float g_K[MTOT*HH];
__device__ float g_V[MTOT*HH];

__device__ __forceinline__ float rna(float x){
    uint32_t u = __float_as_uint(x), o;
    asm("cvt.rna.tf32.f32 %0, %1;" : "=r"(o) : "r"(u));
    return __uint_as_float(o);
}
__device__ __forceinline__ void mma8(float* d, const uint32_t* a, uint32_t b0, uint32_t b1){
    asm volatile(
        "mma.sync.aligned.m16n8k8.row.col.f32.tf32.tf32.f32 "
        "{%0,%1,%2,%3}, {%4,%5,%6,%7}, {%8,%9}, {%0,%1,%2,%3};"
        : "+f"(d[0]), "+f"(d[1]), "+f"(d[2]), "+f"(d[3])
        : "r"(a[0]), "r"(a[1]), "r"(a[2]), "r"(a[3]), "r"(b0), "r"(b1));
}
__device__ __forceinline__ uint32_t f2u(float x){ return __float_as_uint(x); }
__device__ __forceinline__ uint32_t smem_u32(const void* p){
    uint32_t a;
    asm("{ .reg .u64 t; cvta.to.shared.u64 t, %1; cvt.u32.u64 %0, t; }" : "=r"(a) : "l"(p));
    return a;
}
#define CPA16(dst, src) asm volatile("cp.async.cg.shared.global [%0], [%1], 16;" :: "r"(dst), "l"(src))
#define CPA_COMMIT()    asm volatile("cp.async.commit_group;" ::: "memory")
#define CPA_WAIT(n)     asm volatile("cp.async.wait_group %0;" :: "n"(n) : "memory")

// ---------------------------------------------------------------------------
// Projection: [Q|K|V](16384,192) = x(16384,512) @ [Wq*s|Wk|Wv](512,192)
// 256 blocks x 512 threads, 64 rows/block, 2 blocks/SM.
// Warp grid: 2 row-groups (32 rows) x 8 col-groups (24 cols = 3 j-tiles).
// ---------------------------------------------------------------------------
#define XST 68
#define WST 200
#define PJ_SMEM ((64*XST + 64*WST)*4)   // 68,608 B

__global__ __launch_bounds__(512, 2) void proj_mma(
    const float* __restrict__ x,  const float* __restrict__ Wq,
    const float* __restrict__ Wk, const float* __restrict__ Wv)
{
    extern __shared__ float sm[];
    float* xs = sm;              // 64 x 68
    float* ws = sm + 64*XST;     // 64 x 200 (cols 0-63 Wq*s, 64-127 Wk, 128-191 Wv)

    const int tid  = threadIdx.x;
    const int w    = tid >> 5;
    const int lane = tid & 31;
    const int lq   = lane >> 2;
    const int lr   = lane & 3;
    const int rw   = w & 1;          // row group (32 rows)
    const int cw   = w >> 1;         // col group (24 cols = 3 j-tiles)
    const int g0   = blockIdx.x * 64;

    float acc[2][3][4];
    #pragma unroll
    for (int m = 0; m < 2; m++)
        #pragma unroll
        for (int j = 0; j < 3; j++)
            #pragma unroll
            for (int t = 0; t < 4; t++) acc[m][j][t] = 0.f;

    for (int kc = 0; kc < 8; kc++){
        __syncthreads();
        {   // stage x chunk [64 x 64], rounded
            const float* xg = x + (size_t)g0 * CC + kc*64;
            #pragma unroll
            for (int it = 0; it < 2; it++){
                int r = (tid >> 4) + it*32, c4 = (tid & 15) * 4;
                float4 v = *(const float4*)(xg + (size_t)r*CC + c4);
                v.x = rna(v.x); v.y = rna(v.y); v.z = rna(v.z); v.w = rna(v.w);
                *(float4*)(xs + r*XST + c4) = v;
            }
        }
        // stage W chunk [64 x 192], rounded (+SCALE on Wq)
        #pragma unroll
        for (int it = 0; it < 6; it++){
            int i = tid + it*512;
            int k = i / 48, c4 = (i % 48) * 4;
            int g = c4 >> 6, cc = c4 & 63;
            const float* Wg = (g == 0) ? Wq : (g == 1) ? Wk : Wv;
            float s = (g == 0) ? SCALE : 1.f;
            float4 v = *(const float4*)(Wg + (size_t)(kc*64 + k)*HH + cc);
            v.x = rna(v.x*s); v.y = rna(v.y*s); v.z = rna(v.z*s); v.w = rna(v.w*s);
            *(float4*)(ws + k*WST + c4) = v;
        }
        __syncthreads();

        #pragma unroll
        for (int ks = 0; ks < 8; ks++){
            uint32_t a[2][4];
            #pragma unroll
            for (int m = 0; m < 2; m++){
                const float* ab = xs + (32*rw + 16*m + lq)*XST + ks*8 + lr;
                a[m][0] = f2u(ab[0]);   a[m][1] = f2u(ab[8*XST]);
                a[m][2] = f2u(ab[4]);   a[m][3] = f2u(ab[8*XST + 4]);
            }
            #pragma unroll
            for (int j = 0; j < 3; j++){
                const float* bb = ws + (ks*8 + lr)*WST + 24*cw + j*8 + lq;
                uint32_t b0 = f2u(bb[0]), b1 = f2u(bb[4*WST]);
                mma8(acc[0][j], a[0], b0, b1);
                mma8(acc[1][j], a[1], b0, b1);
            }
        }
    }

    // epilogue: round + store
    #pragma unroll
    for (int m = 0; m < 2; m++){
        const int row = g0 + 32*rw + 16*m + lq;
        #pragma unroll
        for (int j = 0; j < 3; j++){
            int c = 24*cw + j*8 + 2*lr;
            int g = c >> 6, cc = c & 63;
            float* dst = (g == 0) ? g_Q : (g == 1) ? g_K : g_V;
            float2 v0 = { rna(acc[m][j][0]), rna(acc[m][j][1]) };
            float2 v1 = { rna(acc[m][j][2]), rna(acc[m][j][3]) };
            *(float2*)(dst + (size_t)row*HH + cc)       = v0;
            *(float2*)(dst + (size_t)(row + 8)*HH + cc) = v1;
        }
    }
}

// ---------------------------------------------------------------------------
// Attention: 128 blocks x 512 threads; 128 q rows/block, 16 tiles of 128 keys.
// Warp grid: S 4 (rows of 32) x 4 (keys of 32); PV 4 (rows of 32) x 4 (hcols of 16).
// K double-buffered, V single-buffered (separate cp.async groups).
// smem floats: lbuf[4][128] @0, Qs@512, Ks0, Ks1, Vs, Ps.
// ---------------------------------------------------------------------------
#define KST 68
#define VST 72
#define PST 132
#define QST 68
#define OF_LB 0
#define OF_Q  512
#define OF_K0 (OF_Q  + 128*QST)   //  9216
#define OF_K1 (OF_K0 + 128*KST)   // 17920
#define OF_V  (OF_K1 + 128*KST)   // 26624
#define OF_P  (OF_V  + 128*VST)   // 35840
#define AT_SMEM ((OF_P + 128*PST)*4)   // 210,944 B

__global__ __launch_bounds__(512, 1) void attn_mma(float* __restrict__ out)
{
    extern __shared__ float sm[];
    const uint32_t sb = smem_u32(sm);
    float* Qs = sm + OF_Q;
    float* Ps = sm + OF_P;
    float* Vs = sm + OF_V;

    const int tid  = threadIdx.x;
    const int w    = tid >> 5;
    const int lane = tid & 31;
    const int lq   = lane >> 2;
    const int lr   = lane & 3;
    const int rw   = w & 3;          // row group (32 rows), both GEMMs
    const int cw   = w >> 2;         // col group: 32 keys (S) / 16 hcols (PV)
    const int g0   = blockIdx.x * 128;
    const int b    = g0 >> 11;

    const int stg_r  = tid >> 4;            // 0..31
    const int stg_c4 = (tid & 15) * 4;

    // prefetch K tile 0 (group 0)
    {
        const float* Kg = g_K + (size_t)(b*TT) * HH;
        #pragma unroll
        for (int it = 0; it < 4; it++){
            int r = stg_r + it*32;
            CPA16(sb + (OF_K0 + r*KST + stg_c4)*4, Kg + (size_t)r*HH + stg_c4);
        }
        CPA_COMMIT();
    }
    // stage Q (already tf32 + pre-scaled)
    {
        const float* Qg = g_Q + (size_t)g0 * HH;
        #pragma unroll
        for (int it = 0; it < 4; it++){
            int r = stg_r + it*32;
            *(float4*)(Qs + r*QST + stg_c4) = *(const float4*)(Qg + (size_t)r*HH + stg_c4);
        }
    }

    float oacc[2][2][4];
    #pragma unroll
    for (int m = 0; m < 2; m++)
        #pragma unroll
        for (int j = 0; j < 2; j++)
            #pragma unroll
            for (int t = 0; t < 4; t++) oacc[m][j][t] = 0.f;
    float ls[2][2] = {{0.f,0.f},{0.f,0.f}};

    for (int kt = 0; kt < 16; kt++){
        if (kt) __syncthreads();   // PV(kt-1) done: V, P, old-K buffers free
        else    __syncthreads();   // Q staging visible

        // issue V(kt) (own group), then K(kt+1) (own group)
        {
            const float* Vg = g_V + (size_t)(b*TT + kt*128) * HH;
            #pragma unroll
            for (int it = 0; it < 4; it++){
                int r = stg_r + it*32;
                CPA16(sb + (OF_V + r*VST + stg_c4)*4, Vg + (size_t)r*HH + stg_c4);
            }
            CPA_COMMIT();
        }
        if (kt + 1 < 16){
            const uint32_t kofs = ((kt+1) & 1) ? OF_K1 : OF_K0;
            const float* Kg = g_K + (size_t)(b*TT + (kt+1)*128) * HH;
            #pragma unroll
            for (int it = 0; it < 4; it++){
                int r = stg_r + it*32;
                CPA16(sb + (kofs + r*KST + stg_c4)*4, Kg + (size_t)r*HH + stg_c4);
            }
        }
        CPA_COMMIT();

        CPA_WAIT(2);               // K(kt) (and everything older) complete
        __syncthreads();

        const float* Ks = sm + ((kt & 1) ? OF_K1 : OF_K0);

        // ---- S = Q @ K^T : rows 32*rw.., keys 32*cw.. (4 n-tiles) ----
        float s[2][4][4];
        #pragma unroll
        for (int m = 0; m < 2; m++)
            #pragma unroll
            for (int j = 0; j < 4; j++)
                #pragma unroll
                for (int t = 0; t < 4; t++) s[m][j][t] = 0.f;

        #pragma unroll
        for (int ks = 0; ks < 8; ks++){
            uint32_t a[2][4];
            #pragma unroll
            for (int m = 0; m < 2; m++){
                const float* ab = Qs + (32*rw + 16*m + lq)*QST + ks*8 + lr;
                a[m][0] = f2u(ab[0]);   a[m][1] = f2u(ab[8*QST]);
                a[m][2] = f2u(ab[4]);   a[m][3] = f2u(ab[8*QST + 4]);
            }
            #pragma unroll
            for (int nt = 0; nt < 4; nt++){
                const float* bb = Ks + (32*cw + nt*8 + lq)*KST + ks*8 + lr;
                uint32_t b0 = f2u(bb[0]), b1 = f2u(bb[4]);
                mma8(s[0][nt], a[0], b0, b1);
                mma8(s[1][nt], a[1], b0, b1);
            }
        }

        // ---- softmax (no max): exp, partial row sums, write P ----
        #pragma unroll
        for (int m = 0; m < 2; m++){
            float* p0 = Ps + (32*rw + 16*m + lq)*PST + 32*cw + 2*lr;
            float* p1 = p0 + 8*PST;
            #pragma unroll
            for (int nt = 0; nt < 4; nt++){
                float e0 = __expf(s[m][nt][0]);
                float e1 = __expf(s[m][nt][1]);
                float e2 = __expf(s[m][nt][2]);
                float e3 = __expf(s[m][nt][3]);
                ls[m][0] += e0 + e1;
                ls[m][1] += e2 + e3;
                float2 w0 = { rna(e0), rna(e1) };
                float2 w1 = { rna(e2), rna(e3) };
                *(float2*)(p0 + nt*8) = w0;
                *(float2*)(p1 + nt*8) = w1;
            }
        }
        CPA_WAIT(1);               // V(kt) complete (K(kt+1) may still fly)
        __syncthreads();           // P + V visible block-wide

        // ---- O += P @ V : rows 32*rw.., hcols 16*cw.. (2 n-tiles), K=128 ----
        #pragma unroll
        for (int ks = 0; ks < 16; ks++){
            uint32_t a[2][4];
            #pragma unroll
            for (int m = 0; m < 2; m++){
                const float* ab = Ps + (32*rw + 16*m + lq)*PST + ks*8 + lr;
                a[m][0] = f2u(ab[0]);   a[m][1] = f2u(ab[8*PST]);
                a[m][2] = f2u(ab[4]);   a[m][3] = f2u(ab[8*PST + 4]);
            }
            #pragma unroll
            for (int nt = 0; nt < 2; nt++){
                const float* bb = Vs + (ks*8 + lr)*VST + 16*cw + nt*8 + lq;
                uint32_t b0 = f2u(bb[0]), b1 = f2u(bb[4*VST]);
                mma8(oacc[0][nt], a[0], b0, b1);
                mma8(oacc[1][nt], a[1], b0, b1);
            }
        }
    }

    // ---- finalize row sums: quad-reduce, combine the 4 col-warps ----
    float* lbuf = sm + OF_LB;   // [4][128]
    #pragma unroll
    for (int m = 0; m < 2; m++)
        #pragma unroll
        for (int h = 0; h < 2; h++){
            float v = ls[m][h];
            v += __shfl_xor_sync(0xffffffffu, v, 1);
            v += __shfl_xor_sync(0xffffffffu, v, 2);
            ls[m][h] = v;
        }
    __syncthreads();
    #pragma unroll
    for (int m = 0; m < 2; m++){
        lbuf[cw*128 + 32*rw + 16*m + lq]     = ls[m][0];
        lbuf[cw*128 + 32*rw + 16*m + lq + 8] = ls[m][1];
    }
    __syncthreads();

    #pragma unroll
    for (int m = 0; m < 2; m++){
        const int row = 32*rw + 16*m + lq;
        const float inv0 = 1.f / (lbuf[row]     + lbuf[128 + row]     + lbuf[256 + row]     + lbuf[384 + row]);
        const float inv1 = 1.f / (lbuf[row + 8] + lbuf[128 + row + 8] + lbuf[256 + row + 8] + lbuf[384 + row + 8]);
        #pragma unroll
        for (int nt = 0; nt < 2; nt++){
            int col = 16*cw + nt*8 + 2*lr;
            float2 v0 = { oacc[m][nt][0]*inv0, oacc[m][nt][1]*inv0 };
            float2 v1 = { oacc[m][nt][2]*inv1, oacc[m][nt][3]*inv1 };
            *(float2*)(out + (size_t)(g0 + row)*HH + col)     = v0;
            *(float2*)(out + (size_t)(g0 + row + 8)*HH + col) = v1;
        }
    }
}

// ---------------------------------------------------------------------------
extern "C" void kernel_launch(void* const* d_in, const int* in_sizes, int n_in,
                              void* d_out, int out_size)
{
    const float* x  = (const float*)d_in[0];
    const float* Wq = (const float*)d_in[1];
    const float* Wk = (const float*)d_in[2];
    const float* Wv = (const float*)d_in[3];
    float* out = (float*)d_out;

    cudaFuncSetAttribute(proj_mma, cudaFuncAttributeMaxDynamicSharedMemorySize, PJ_SMEM);
    proj_mma<<<MTOT/64, 512, PJ_SMEM>>>(x, Wq, Wk, Wv);

    cudaFuncSetAttribute(attn_mma, cudaFuncAttributeMaxDynamicSharedMemorySize, AT_SMEM);
    attn_mma<<<MTOT/128, 512, AT_SMEM>>>(out);
}